// round 1
// baseline (speedup 1.0000x reference)
#include <cuda_runtime.h>
#include <stdint.h>

#define NN 2048
#define NW 64   // 2048 bits = 64 u32 words per bit-row

// ---------------- device scratch (static allocation only) ----------------
__device__ uint32_t g_apRow[NN*NW];       // A_pos row-major bits
__device__ uint32_t g_apT[NN*NW];         // A_pos^T bits: apT[j] word w bit b <-> Ap(k=w*32+b, j)
__device__ uint32_t g_lastT0[NN*NW];      // last^T bits (double buffered)
__device__ uint32_t g_lastT1[NN*NW];
__device__ uint32_t g_unionRow[NN*NW];    // union, row-major bits
__device__ unsigned short g_aptIdx[NN*NN];// CSR of Ap columns (capacity = N, safe)
__device__ int      g_aptCnt[NN];
__device__ float    g_dinv[NN];
__device__ int      g_pc[NN];
__device__ float    g_bufA[NN*256];
__device__ float    g_bufB[NN*256];
__device__ float    g_bufG[NN*256];
__device__ float    g_colsum[256];

// ---------------- pack dense float rows -> bit rows ----------------
__global__ void pack_rows_kernel(const float* __restrict__ A, uint32_t* __restrict__ bits)
{
    int idx = blockIdx.x*blockDim.x + threadIdx.x; // i*64 + w
    if (idx >= NN*NW) return;
    int i = idx >> 6, w = idx & 63;
    const float4* p = (const float4*)(A + (size_t)i*NN + w*32);
    uint32_t m = 0;
#pragma unroll
    for (int q = 0; q < 8; q++) {
        float4 v = p[q];
        if (v.x > 0.f) m |= 1u << (q*4+0);
        if (v.y > 0.f) m |= 1u << (q*4+1);
        if (v.z > 0.f) m |= 1u << (q*4+2);
        if (v.w > 0.f) m |= 1u << (q*4+3);
    }
    bits[idx] = m;
}

// ---------------- 2048x2048 bit transpose (32x32 tiles via ballot) ----------------
// out[j][wi] bit b = in[i=wi*32+b][wj covering j].  orInto: out |= transposed.
__global__ void bit_transpose_kernel(const uint32_t* __restrict__ in, uint32_t* __restrict__ out, int orInto)
{
    int warp = (blockIdx.x*blockDim.x + threadIdx.x) >> 5;
    int lane = threadIdx.x & 31;
    if (warp >= 64*64) return;
    int ti = warp >> 6;     // input row block
    int tj = warp & 63;     // input word index
    uint32_t v = in[(ti*32 + lane)*NW + tj];
#pragma unroll
    for (int jb = 0; jb < 32; jb++) {
        uint32_t w = __ballot_sync(0xffffffffu, (v >> jb) & 1u);
        if (lane == jb) {
            int o = (tj*32 + jb)*NW + ti;
            out[o] = orInto ? (out[o] | w) : w;
        }
    }
}

// ---------------- CSR of Ap columns from apT bits ----------------
__global__ void build_csr_kernel(const uint32_t* __restrict__ apT,
                                 unsigned short* __restrict__ idxArr, int* __restrict__ cnt)
{
    int j = blockIdx.x*blockDim.x + threadIdx.x;
    if (j >= NN) return;
    int c = 0;
    unsigned short* dst = idxArr + (size_t)j*NN;
    for (int w = 0; w < NW; w++) {
        uint32_t m = apT[j*NW + w];
        while (m) { int b = __ffs(m)-1; m &= (m-1); dst[c++] = (unsigned short)(w*32 + b); }
    }
    cnt[j] = c;
}

// ---------------- boolean expansion in transposed domain ----------------
// newLastT[j] = OR_{k in col_j(Ap)} lastT_old[k]
__global__ void expandT_kernel(const uint32_t* __restrict__ lastOld, uint32_t* __restrict__ lastNew,
                               const unsigned short* __restrict__ idxArr, const int* __restrict__ cnt)
{
    int w = threadIdx.x;                          // 0..63 (word lane)
    int j = blockIdx.x*blockDim.y + threadIdx.y;  // row of lastT
    int c = cnt[j];
    const unsigned short* lst = idxArr + (size_t)j*NN;
    uint32_t acc = 0;
    for (int t = 0; t < c; t++) {
        int k = lst[t];
        acc |= lastOld[k*NW + w];
    }
    lastNew[j*NW + w] = acc;
}

// ---------------- degrees: deg = popcount(union row) + 1 ----------------
__global__ void degrees_kernel(const uint32_t* __restrict__ unionRow,
                               float* __restrict__ dinv, int* __restrict__ pc)
{
    int i = blockIdx.x*blockDim.x + threadIdx.x;
    if (i >= NN) return;
    const uint4* p = (const uint4*)(unionRow + i*NW);
    int s = 0;
#pragma unroll
    for (int q = 0; q < 16; q++) {
        uint4 v = p[q];
        s += __popc(v.x)+__popc(v.y)+__popc(v.z)+__popc(v.w);
    }
    pc[i] = s;
    dinv[i] = rsqrtf((float)(s+1));
}

// ---------------- simple tiled SGEMM: C[2048 x N] = A[2048 x K] @ W[K x N] (+bias) ----------------
__global__ void sgemm_bias_kernel(const float* __restrict__ A, int lda,
                                  const float* __restrict__ W, int ldw,
                                  const float* __restrict__ bias,
                                  float* __restrict__ C, int ldc,
                                  int K, int N)
{
    __shared__ __align__(16) float As[8][68];
    __shared__ __align__(16) float Ws[8][64];
    int tid = threadIdx.x;
    int tx = tid & 15, ty = tid >> 4;
    int rowBase = blockIdx.y * 64;
    int colBase = blockIdx.x * 64;

    float acc[4][4];
#pragma unroll
    for (int a = 0; a < 4; a++)
#pragma unroll
        for (int b = 0; b < 4; b++) acc[a][b] = 0.f;

    for (int k0 = 0; k0 < K; k0 += 8) {
        // A tile: 64 rows x 8 k  (thread -> 2 consecutive k of one row)
        {
            int m  = tid >> 2;
            int kb = (tid & 3) * 2;
#pragma unroll
            for (int l = 0; l < 2; l++) {
                int kk = kb + l;
                As[kk][m] = (k0+kk < K) ? A[(size_t)(rowBase+m)*lda + k0 + kk] : 0.f;
            }
        }
        // W tile: 8 k x 64 n
        {
            int kk = tid >> 5;
            int nb = (tid & 31) * 2;
#pragma unroll
            for (int l = 0; l < 2; l++) {
                int n = nb + l;
                Ws[kk][n] = (k0+kk < K && colBase+n < N) ? W[(size_t)(k0+kk)*ldw + colBase + n] : 0.f;
            }
        }
        __syncthreads();
#pragma unroll
        for (int kk = 0; kk < 8; kk++) {
            float4 av = *(const float4*)&As[kk][ty*4];
            float4 bv = *(const float4*)&Ws[kk][tx*4];
            float a4[4] = {av.x, av.y, av.z, av.w};
            float b4[4] = {bv.x, bv.y, bv.z, bv.w};
#pragma unroll
            for (int a = 0; a < 4; a++)
#pragma unroll
                for (int b = 0; b < 4; b++)
                    acc[a][b] += a4[a] * b4[b];
        }
        __syncthreads();
    }
#pragma unroll
    for (int a = 0; a < 4; a++) {
        int row = rowBase + ty*4 + a;
#pragma unroll
        for (int b = 0; b < 4; b++) {
            int col = colBase + tx*4 + b;
            if (col < N)
                C[(size_t)row*ldc + col] = acc[a][b] + (bias ? bias[col] : 0.f);
        }
    }
}

// ---------------- column sums of t = dinv .* g (for complement trick) ----------------
__global__ void colsum_kernel(const float* __restrict__ g, int ldg, const float* __restrict__ dinv,
                              float* __restrict__ cs, int Nf)
{
    int f = blockIdx.x*64 + threadIdx.x;
    int part = threadIdx.y;  // 0..3
    float s = 0.f;
    if (f < Nf) {
        for (int k = part*512; k < (part+1)*512; k++)
            s += dinv[k] * g[(size_t)k*ldg + f];
    }
    __shared__ float sh[4][64];
    sh[part][threadIdx.x] = s;
    __syncthreads();
    if (part == 0)
        cs[f] = sh[0][threadIdx.x]+sh[1][threadIdx.x]+sh[2][threadIdx.x]+sh[3][threadIdx.x];
}

// ---------------- fused aggregation + GCN epilogue ----------------
// out = h + w * act( dinv_i * ( sum_k union(i,k) t_k + t_i ) + b_g ),  t = dinv .* g
// Per-row complement: if popcount > 1024, sum = colsum - sum over UNSET bits.
template<int FPAD, int RT>
__global__ void agg_kernel(const float* __restrict__ h, int ldh,
                           const float* __restrict__ g, int ldg,
                           const float* __restrict__ dinv,
                           const int* __restrict__ pc,
                           const uint32_t* __restrict__ unionRow,
                           const float* __restrict__ colsum,
                           const float* __restrict__ bias,
                           float* __restrict__ out, int ldo,
                           int Nf, float wscale, int doRelu)
{
    constexpr int LANES   = FPAD/4;
    constexpr int GROUPS  = 32/RT;
    constexpr int THREADS = LANES*GROUPS;
    __shared__ __align__(16) float sT[32*FPAD];

    int tid   = threadIdx.x;
    int flane = tid % LANES;
    int grp   = tid / LANES;
    int i0    = blockIdx.x*32;

    float4 acc[RT];
    int    rows[RT];
    bool   comp[RT];
#pragma unroll
    for (int r = 0; r < RT; r++) {
        rows[r] = i0 + grp*RT + r;
        comp[r] = pc[rows[r]] > 1024;
        acc[r]  = make_float4(0.f,0.f,0.f,0.f);
    }

    for (int kc = 0; kc < NW; kc++) {
        int k0 = kc*32;
        for (int idx = tid; idx < 32*FPAD; idx += THREADS) {
            int kk = idx / FPAD;
            int f  = idx - kk*FPAD;
            float v = 0.f;
            if (f < Nf) v = dinv[k0+kk] * g[(size_t)(k0+kk)*ldg + f];
            sT[idx] = v;
        }
        __syncthreads();
#pragma unroll
        for (int r = 0; r < RT; r++) {
            uint32_t m = unionRow[rows[r]*NW + kc];
            if (comp[r]) m = ~m;
            while (m) {
                int b = __ffs(m)-1; m &= (m-1);
                const float4 v = *(const float4*)&sT[b*FPAD + flane*4];
                acc[r].x += v.x; acc[r].y += v.y; acc[r].z += v.z; acc[r].w += v.w;
            }
        }
        __syncthreads();
    }

    float4 cs = *(const float4*)&colsum[flane*4];
#pragma unroll
    for (int r = 0; r < RT; r++) {
        int i = rows[r];
        float4 S = acc[r];
        if (comp[r]) { S.x = cs.x - S.x; S.y = cs.y - S.y; S.z = cs.z - S.z; S.w = cs.w - S.w; }
        float di = dinv[i];
        float Sa[4] = {S.x, S.y, S.z, S.w};
#pragma unroll
        for (int c = 0; c < 4; c++) {
            int f = flane*4 + c;
            if (f < Nf) {
                float ti  = di * g[(size_t)i*ldg + f];
                float val = di * (Sa[c] + ti) + bias[f];
                if (doRelu) val = fmaxf(val, 0.f);
                out[(size_t)i*ldo + f] = h[(size_t)i*ldh + f] + wscale*val;
            }
        }
    }
}

// ---------------- host orchestration ----------------
static void* sym(const void* s) { void* p = nullptr; cudaGetSymbolAddress(&p, s); return p; }

extern "C" void kernel_launch(void* const* d_in, const int* in_sizes, int n_in,
                              void* d_out, int out_size)
{
    const float* x    = (const float*)d_in[0];
    const float* Aneg = (const float*)d_in[1];
    const float* Apos = (const float*)d_in[2];
    const float* W_l1 = (const float*)d_in[3];  const float* b_l1 = (const float*)d_in[4];
    const float* W_l2 = (const float*)d_in[5];  const float* b_l2 = (const float*)d_in[6];
    const float* W_l3 = (const float*)d_in[7];  const float* b_l3 = (const float*)d_in[8];
    const float* W_g1 = (const float*)d_in[9];  const float* b_g1 = (const float*)d_in[10];
    const float* W_g2 = (const float*)d_in[11]; const float* b_g2 = (const float*)d_in[12];
    const float* W_g3 = (const float*)d_in[13]; const float* b_g3 = (const float*)d_in[14];
    const float* W_g4 = (const float*)d_in[15]; const float* b_g4 = (const float*)d_in[16];
    const float* W_g5 = (const float*)d_in[17]; const float* b_g5 = (const float*)d_in[18];
    const float* W_g6 = (const float*)d_in[19]; const float* b_g6 = (const float*)d_in[20];
    float* out = (float*)d_out;

    uint32_t* apRow    = (uint32_t*)sym(g_apRow);
    uint32_t* apT      = (uint32_t*)sym(g_apT);
    uint32_t* lastT0   = (uint32_t*)sym(g_lastT0);
    uint32_t* lastT1   = (uint32_t*)sym(g_lastT1);
    uint32_t* unionRow = (uint32_t*)sym(g_unionRow);
    unsigned short* aptIdx = (unsigned short*)sym(g_aptIdx);
    int*    aptCnt = (int*)sym(g_aptCnt);
    float*  dinv   = (float*)sym(g_dinv);
    int*    pc     = (int*)sym(g_pc);
    float*  bufA   = (float*)sym(g_bufA);
    float*  bufB   = (float*)sym(g_bufB);
    float*  bufG   = (float*)sym(g_bufG);
    float*  cs     = (float*)sym(g_colsum);

    dim3 tpose_grid(512), tpose_blk(256);
    dim3 exp_blk(64,8);
    dim3 cs_blk(64,4);

    // ---- preprocessing ----
    pack_rows_kernel<<<512,256>>>(Apos, apRow);
    bit_transpose_kernel<<<tpose_grid,tpose_blk>>>(apRow, apT, 0);
    build_csr_kernel<<<8,256>>>(apT, aptIdx, aptCnt);
    pack_rows_kernel<<<512,256>>>(Aneg, unionRow);          // union0 = A_neg (row bits)
    bit_transpose_kernel<<<tpose_grid,tpose_blk>>>(unionRow, lastT0, 0); // lastT = A_neg^T

    // ---- stage 1 (F=256, w=1, relu) ----
    degrees_kernel<<<8,256>>>(unionRow, dinv, pc);
    sgemm_bias_kernel<<<dim3(4,32),256>>>(x,   512, W_l1, 256, b_l1, bufA, 256, 512, 256); // h1
    sgemm_bias_kernel<<<dim3(4,32),256>>>(bufA,256, W_g1, 256, nullptr, bufG, 256, 256, 256); // g1
    colsum_kernel<<<4,cs_blk>>>(bufG, 256, dinv, cs, 256);
    agg_kernel<256,4><<<64,512>>>(bufA,256, bufG,256, dinv,pc,unionRow, cs, b_g1, bufB,256, 256, 1.0f, 1);

    // ---- stage 2 (F=62, w=1, relu) ----
    expandT_kernel<<<256,exp_blk>>>(lastT0, lastT1, aptIdx, aptCnt);
    bit_transpose_kernel<<<tpose_grid,tpose_blk>>>(lastT1, unionRow, 1);
    degrees_kernel<<<8,256>>>(unionRow, dinv, pc);
    sgemm_bias_kernel<<<dim3(1,32),256>>>(bufB,256, W_l2, 62, b_l2, bufA, 64, 256, 62); // h2
    sgemm_bias_kernel<<<dim3(1,32),256>>>(bufA, 64, W_g2, 62, nullptr, bufG, 64, 62, 62); // g2
    colsum_kernel<<<1,cs_blk>>>(bufG, 64, dinv, cs, 62);
    agg_kernel<64,1><<<64,512>>>(bufA,64, bufG,64, dinv,pc,unionRow, cs, b_g2, bufB,64, 62, 1.0f, 1);

    // ---- stage 3 (F=64, w=0.5, relu) ----
    expandT_kernel<<<256,exp_blk>>>(lastT1, lastT0, aptIdx, aptCnt);
    bit_transpose_kernel<<<tpose_grid,tpose_blk>>>(lastT0, unionRow, 1);
    degrees_kernel<<<8,256>>>(unionRow, dinv, pc);
    sgemm_bias_kernel<<<dim3(1,32),256>>>(bufB,64, W_l3, 64, b_l3, bufA, 64, 62, 64); // h3
    sgemm_bias_kernel<<<dim3(1,32),256>>>(bufA,64, W_g3, 64, nullptr, bufG, 64, 64, 64); // g3
    colsum_kernel<<<1,cs_blk>>>(bufG, 64, dinv, cs, 64);
    agg_kernel<64,1><<<64,512>>>(bufA,64, bufG,64, dinv,pc,unionRow, cs, b_g3, bufB,64, 64, 0.5f, 1);

    // ---- stage 4 (h = x3, w=0.5, relu) ----
    expandT_kernel<<<256,exp_blk>>>(lastT0, lastT1, aptIdx, aptCnt);
    bit_transpose_kernel<<<tpose_grid,tpose_blk>>>(lastT1, unionRow, 1);
    degrees_kernel<<<8,256>>>(unionRow, dinv, pc);
    sgemm_bias_kernel<<<dim3(1,32),256>>>(bufB,64, W_g4, 64, nullptr, bufG, 64, 64, 64);
    colsum_kernel<<<1,cs_blk>>>(bufG, 64, dinv, cs, 64);
    agg_kernel<64,1><<<64,512>>>(bufB,64, bufG,64, dinv,pc,unionRow, cs, b_g4, bufA,64, 64, 0.5f, 1);

    // ---- stage 5 (h = x4, w=0.25, relu) ----
    expandT_kernel<<<256,exp_blk>>>(lastT1, lastT0, aptIdx, aptCnt);
    bit_transpose_kernel<<<tpose_grid,tpose_blk>>>(lastT0, unionRow, 1);
    degrees_kernel<<<8,256>>>(unionRow, dinv, pc);
    sgemm_bias_kernel<<<dim3(1,32),256>>>(bufA,64, W_g5, 64, nullptr, bufG, 64, 64, 64);
    colsum_kernel<<<1,cs_blk>>>(bufG, 64, dinv, cs, 64);
    agg_kernel<64,1><<<64,512>>>(bufA,64, bufG,64, dinv,pc,unionRow, cs, b_g5, bufB,64, 64, 0.25f, 1);

    // ---- stage 6 (h = x5, w=0.25, NO relu) -> d_out ----
    expandT_kernel<<<256,exp_blk>>>(lastT0, lastT1, aptIdx, aptCnt);
    bit_transpose_kernel<<<tpose_grid,tpose_blk>>>(lastT1, unionRow, 1);
    degrees_kernel<<<8,256>>>(unionRow, dinv, pc);
    sgemm_bias_kernel<<<dim3(1,32),256>>>(bufB,64, W_g6, 64, nullptr, bufG, 64, 64, 64);
    colsum_kernel<<<1,cs_blk>>>(bufG, 64, dinv, cs, 64);
    agg_kernel<64,1><<<64,512>>>(bufB,64, bufG,64, dinv,pc,unionRow, cs, b_g6, out,64, 64, 0.25f, 0);
}

// round 2
// speedup vs baseline: 2.4298x; 2.4298x over previous
#include <cuda_runtime.h>
#include <stdint.h>

#define NN 2048
#define NW 64   // 2048 bits = 64 u32 words

// ---------------- device scratch ----------------
__device__ uint32_t g_apT[NN*NW];       // A_pos^T bits
__device__ uint32_t g_lastT0[NN*NW];
__device__ uint32_t g_lastT1[NN*NW];
__device__ uint32_t g_unionRow[NN*NW];
__device__ int      g_pc[NN];           // popcount(union row)
__device__ float    g_cs[512];          // column sums of dinv.*g
__device__ float    g_Wbig1[512*512];
__device__ float    g_bbig1[512];
__device__ float    g_Wbig2[256*128];
__device__ float    g_bbig2[128];
__device__ float    g_Wbig3[64*128];
__device__ float    g_bbig3[128];
__device__ float    g_bufC[NN*512];     // GEMM outputs
__device__ float    g_bufX[NN*256];
__device__ float    g_bufY[NN*64];

// ---------------- pack A_pos -> transposed bits only; zero pc & cs ----------------
__global__ void packT_pos_kernel(const float* __restrict__ A, uint32_t* __restrict__ apT,
                                 int* __restrict__ pc, float* __restrict__ cs)
{
    int gwarp = (blockIdx.x*blockDim.x + threadIdx.x) >> 5;
    int lane  = threadIdx.x & 31;
    int ti = gwarp >> 6;   // row tile (32 rows)
    int tj = gwarp & 63;   // col tile (32 cols)
    uint32_t tbits = 0;
#pragma unroll
    for (int r = 0; r < 32; r++) {
        float v = A[(size_t)(ti*32 + r)*NN + tj*32 + lane];
        tbits |= (v > 0.f ? 1u : 0u) << r;
    }
    apT[(tj*32 + lane)*NW + ti] = tbits;
    if (blockIdx.x == 0) {
        for (int t = threadIdx.x; t < NN; t += blockDim.x) pc[t] = 0;
        for (int t = threadIdx.x; t < 512; t += blockDim.x) cs[t] = 0.f;
    }
}

// ---------------- pack A_neg -> unionRow (row bits) + lastT (transposed) + pc ----------------
__global__ void pack_neg_kernel(const float* __restrict__ A, uint32_t* __restrict__ unionRow,
                                uint32_t* __restrict__ lastT, int* __restrict__ pc)
{
    int gwarp = (blockIdx.x*blockDim.x + threadIdx.x) >> 5;
    int lane  = threadIdx.x & 31;
    int ti = gwarp >> 6;
    int tj = gwarp & 63;
    uint32_t tbits = 0, rw = 0;
#pragma unroll
    for (int r = 0; r < 32; r++) {
        float v = A[(size_t)(ti*32 + r)*NN + tj*32 + lane];
        uint32_t b = (v > 0.f) ? 1u : 0u;
        tbits |= b << r;
        uint32_t m = __ballot_sync(0xffffffffu, b);
        if (lane == r) rw = m;
    }
    unionRow[(ti*32 + lane)*NW + tj] = rw;
    atomicAdd(&pc[ti*32 + lane], __popc(rw));
    lastT[(tj*32 + lane)*NW + ti] = tbits;
}

// ---------------- weight pre-association: Wbig = [W_l | W_l@W_g], bbig = [b_l | b_l@W_g] ----------------
__global__ void wprep_kernel(const float* __restrict__ W_l1, const float* __restrict__ b_l1, const float* __restrict__ W_g1,
                             const float* __restrict__ W_l2, const float* __restrict__ b_l2, const float* __restrict__ W_g2,
                             const float* __restrict__ W_l3, const float* __restrict__ b_l3, const float* __restrict__ W_g3,
                             float* __restrict__ Wbig1, float* __restrict__ bbig1,
                             float* __restrict__ Wbig2, float* __restrict__ bbig2,
                             float* __restrict__ Wbig3, float* __restrict__ bbig3)
{
    int idx = blockIdx.x*blockDim.x + threadIdx.x;
    if (idx < 262144) {                       // Wbig1: 512 x 512
        int k = idx >> 9, c = idx & 511;
        float v;
        if (c < 256) v = W_l1[k*256 + c];
        else { float s = 0.f; int cc = c-256; for (int j = 0; j < 256; j++) s += W_l1[k*256+j]*W_g1[j*256+cc]; v = s; }
        Wbig1[idx] = v;
    } else if (idx < 262656) {                // bbig1: 512
        int c = idx - 262144; float v;
        if (c < 256) v = b_l1[c];
        else { float s = 0.f; int cc = c-256; for (int j = 0; j < 256; j++) s += b_l1[j]*W_g1[j*256+cc]; v = s; }
        bbig1[c] = v;
    } else if (idx < 295424) {                // Wbig2: 256 x 128
        int i = idx - 262656; int k = i >> 7, c = i & 127; float v = 0.f;
        if (c < 62) v = W_l2[k*62 + c];
        else if (c >= 64 && c < 126) { float s = 0.f; int cc = c-64; for (int j = 0; j < 62; j++) s += W_l2[k*62+j]*W_g2[j*62+cc]; v = s; }
        Wbig2[i] = v;
    } else if (idx < 295552) {                // bbig2: 128
        int c = idx - 295424; float v = 0.f;
        if (c < 62) v = b_l2[c];
        else if (c >= 64 && c < 126) { float s = 0.f; int cc = c-64; for (int j = 0; j < 62; j++) s += b_l2[j]*W_g2[j*62+cc]; v = s; }
        bbig2[c] = v;
    } else if (idx < 303744) {                // Wbig3: 64 x 128 (rows 62,63 = 0)
        int i = idx - 295552; int k = i >> 7, c = i & 127; float v = 0.f;
        if (k < 62) {
            if (c < 64) v = W_l3[k*64 + c];
            else { float s = 0.f; int cc = c-64; for (int j = 0; j < 64; j++) s += W_l3[k*64+j]*W_g3[j*64+cc]; v = s; }
        }
        Wbig3[i] = v;
    } else if (idx < 303872) {                // bbig3: 128
        int c = idx - 303744; float v;
        if (c < 64) v = b_l3[c];
        else { float s = 0.f; int cc = c-64; for (int j = 0; j < 64; j++) s += b_l3[j]*W_g3[j*64+cc]; v = s; }
        bbig3[c] = v;
    }
}

// ---------------- expansion in transposed domain + zero pc/cs for this stage ----------------
// lastNew[j] = OR_{k in col_j(Ap)} lastOld[k]
__global__ void expandT_kernel(const uint32_t* __restrict__ lastOld, uint32_t* __restrict__ lastNew,
                               const uint32_t* __restrict__ apT, int* __restrict__ pc, float* __restrict__ cs)
{
    __shared__ uint32_t sh[4][64];
    int w = threadIdx.x;                  // 0..63
    int y = threadIdx.y;                  // 0..3
    int j = blockIdx.x*4 + y;
    sh[y][w] = apT[j*NW + w];
    __syncthreads();
    uint32_t acc = 0;
    for (int w2 = 0; w2 < NW; w2++) {
        uint32_t m = sh[y][w2];
        while (m) {
            int b = __ffs(m) - 1; m &= (m-1);
            acc |= lastOld[(w2*32 + b)*NW + w];
        }
    }
    lastNew[j*NW + w] = acc;
    if (blockIdx.x == 0 && y == 0) { for (int t = w; t < NN;  t += 64) pc[t] = 0; }
    if (blockIdx.x == 1 && y == 0) { for (int t = w; t < 512; t += 64) cs[t] = 0.f; }
}

// ---------------- transpose lastNew, OR into unionRow, accumulate pc ----------------
__global__ void transpose_or_kernel(const uint32_t* __restrict__ lastNew,
                                    uint32_t* __restrict__ unionRow, int* __restrict__ pc)
{
    __shared__ uint32_t sh[32][65];
    int tid = threadIdx.x;
    int ti = blockIdx.x;                  // 32 input rows: ti*32..+31
    for (int idx = tid; idx < 32*64; idx += blockDim.x) {
        int r = idx >> 6, c = idx & 63;
        sh[r][c] = lastNew[(ti*32 + r)*NW + c];
    }
    __syncthreads();
    int warp = tid >> 5, lane = tid & 31;
    for (int tj = warp; tj < 64; tj += 8) {
        uint32_t v = sh[lane][tj];
        uint32_t ow = 0;
#pragma unroll
        for (int jb = 0; jb < 32; jb++) {
            uint32_t m = __ballot_sync(0xffffffffu, (v >> jb) & 1u);
            if (lane == jb) ow = m;
        }
        int j = tj*32 + lane;
        uint32_t merged = unionRow[j*NW + ti] | ow;
        unionRow[j*NW + ti] = merged;
        atomicAdd(&pc[j], __popc(merged));
    }
}

// ---------------- tiled SGEMM with bias + fused colsum (cs[c-gOff] += dinv_r * C[r][c]) ----------------
__global__ void gemm_cs_kernel(const float* __restrict__ A, int lda,
                               const float* __restrict__ W, int ldw,
                               const float* __restrict__ bias,
                               float* __restrict__ C, int ldc,
                               int K, int N,
                               const int* __restrict__ pc,
                               float* __restrict__ cs, int gOff)
{
    __shared__ __align__(16) float As[8][68];
    __shared__ __align__(16) float Ws[8][64];
    __shared__ float red[16][64];
    int tid = threadIdx.x;
    int tx = tid & 15, ty = tid >> 4;
    int rowBase = blockIdx.y * 64;
    int colBase = blockIdx.x * 64;

    float acc[4][4];
#pragma unroll
    for (int a = 0; a < 4; a++)
#pragma unroll
        for (int b = 0; b < 4; b++) acc[a][b] = 0.f;

    for (int k0 = 0; k0 < K; k0 += 8) {
        {
            int m  = tid >> 2;
            int kb = (tid & 3) * 2;
#pragma unroll
            for (int l = 0; l < 2; l++) {
                int kk = kb + l;
                As[kk][m] = (k0+kk < K) ? A[(size_t)(rowBase+m)*lda + k0 + kk] : 0.f;
            }
        }
        {
            int kk = tid >> 5;
            int nb = (tid & 31) * 2;
#pragma unroll
            for (int l = 0; l < 2; l++) {
                int n = nb + l;
                Ws[kk][n] = (k0+kk < K) ? W[(size_t)(k0+kk)*ldw + colBase + n] : 0.f;
            }
        }
        __syncthreads();
#pragma unroll
        for (int kk = 0; kk < 8; kk++) {
            float4 av = *(const float4*)&As[kk][ty*4];
            float4 bv = *(const float4*)&Ws[kk][tx*4];
            float a4[4] = {av.x, av.y, av.z, av.w};
            float b4[4] = {bv.x, bv.y, bv.z, bv.w};
#pragma unroll
            for (int a = 0; a < 4; a++)
#pragma unroll
                for (int b = 0; b < 4; b++)
                    acc[a][b] += a4[a] * b4[b];
        }
        __syncthreads();
    }

    float p[4] = {0.f, 0.f, 0.f, 0.f};
#pragma unroll
    for (int a = 0; a < 4; a++) {
        int row = rowBase + ty*4 + a;
        float di = rsqrtf((float)(pc[row] + 1));
#pragma unroll
        for (int b = 0; b < 4; b++) {
            int col = colBase + tx*4 + b;
            float val = acc[a][b] + (bias ? bias[col] : 0.f);
            C[(size_t)row*ldc + col] = val;
            if (col >= gOff) p[b] += di * val;
        }
    }
#pragma unroll
    for (int b = 0; b < 4; b++) red[ty][tx*4 + b] = p[b];
    __syncthreads();
    if (tid < 64) {
        int col = colBase + tid;
        if (col >= gOff) {
            float s = 0.f;
#pragma unroll
            for (int t = 0; t < 16; t++) s += red[t][tid];
            atomicAdd(&cs[col - gOff], s);
        }
    }
}

// ---------------- syncless fused aggregation + GCN epilogue ----------------
// out = h + w*act( dinv_i*(S + dinv_i*g_i) + b ),  S = sum_{k in union row} dinv_k g_k
// complement trick: if pc>1024, S = cs - sum over UNSET bits.
template<int LANES, int RPB>
__global__ void agg_kernel(const float* __restrict__ h, int ldh,
                           const float* __restrict__ g, int ldg,
                           const int* __restrict__ pc,
                           const uint32_t* __restrict__ unionRow,
                           const float* __restrict__ cs,
                           const float* __restrict__ bias,
                           float* __restrict__ out, int ldo,
                           int Nf, float wscale, int doRelu)
{
    int tid = threadIdx.x;
    int flane = tid % LANES;
    int grp = tid / LANES;
    int row = blockIdx.x*RPB + grp;
    int f = flane*4;
    int myPc = pc[row];
    bool comp = myPc > 1024;
    float di = rsqrtf((float)(myPc + 1));
    float4 acc = make_float4(0.f,0.f,0.f,0.f);
    const uint32_t* ur = unionRow + row*NW;
    for (int w2 = 0; w2 < NW; w2++) {
        uint32_t m = ur[w2];
        if (comp) m = ~m;
        int kbase = w2*32;
        while (m) {
            int b = __ffs(m) - 1; m &= (m-1);
            int k = kbase + b;
            float dk = rsqrtf((float)(pc[k] + 1));
            float4 v = *(const float4*)(g + (size_t)k*ldg + f);
            acc.x += dk*v.x; acc.y += dk*v.y; acc.z += dk*v.z; acc.w += dk*v.w;
        }
    }
    float S[4] = {acc.x, acc.y, acc.z, acc.w};
    if (comp) {
        float4 c4 = *(const float4*)(cs + f);
        S[0] = c4.x - S[0]; S[1] = c4.y - S[1]; S[2] = c4.z - S[2]; S[3] = c4.w - S[3];
    }
    float4 gi = *(const float4*)(g + (size_t)row*ldg + f);
    float4 hv = *(const float4*)(h + (size_t)row*ldh + f);
    float gia[4] = {gi.x, gi.y, gi.z, gi.w};
    float ha[4]  = {hv.x, hv.y, hv.z, hv.w};
#pragma unroll
    for (int c = 0; c < 4; c++) {
        int ff = f + c;
        if (ff < Nf) {
            float val = di*(S[c] + di*gia[c]) + bias[ff];
            if (doRelu) val = fmaxf(val, 0.f);
            out[(size_t)row*ldo + ff] = ha[c] + wscale*val;
        }
    }
}

// ---------------- host ----------------
static void* sym(const void* s) { void* p = nullptr; cudaGetSymbolAddress(&p, s); return p; }

extern "C" void kernel_launch(void* const* d_in, const int* in_sizes, int n_in,
                              void* d_out, int out_size)
{
    const float* x    = (const float*)d_in[0];
    const float* Aneg = (const float*)d_in[1];
    const float* Apos = (const float*)d_in[2];
    const float* W_l1 = (const float*)d_in[3];  const float* b_l1 = (const float*)d_in[4];
    const float* W_l2 = (const float*)d_in[5];  const float* b_l2 = (const float*)d_in[6];
    const float* W_l3 = (const float*)d_in[7];  const float* b_l3 = (const float*)d_in[8];
    const float* W_g1 = (const float*)d_in[9];  const float* b_g1 = (const float*)d_in[10];
    const float* W_g2 = (const float*)d_in[11]; const float* b_g2 = (const float*)d_in[12];
    const float* W_g3 = (const float*)d_in[13]; const float* b_g3 = (const float*)d_in[14];
    const float* W_g4 = (const float*)d_in[15]; const float* b_g4 = (const float*)d_in[16];
    const float* W_g5 = (const float*)d_in[17]; const float* b_g5 = (const float*)d_in[18];
    const float* W_g6 = (const float*)d_in[19]; const float* b_g6 = (const float*)d_in[20];
    float* out = (float*)d_out;

    uint32_t* apT      = (uint32_t*)sym(g_apT);
    uint32_t* lastT0   = (uint32_t*)sym(g_lastT0);
    uint32_t* lastT1   = (uint32_t*)sym(g_lastT1);
    uint32_t* unionRow = (uint32_t*)sym(g_unionRow);
    int*   pc   = (int*)sym(g_pc);
    float* cs   = (float*)sym(g_cs);
    float* Wb1  = (float*)sym(g_Wbig1); float* bb1 = (float*)sym(g_bbig1);
    float* Wb2  = (float*)sym(g_Wbig2); float* bb2 = (float*)sym(g_bbig2);
    float* Wb3  = (float*)sym(g_Wbig3); float* bb3 = (float*)sym(g_bbig3);
    float* bufC = (float*)sym(g_bufC);
    float* bufX = (float*)sym(g_bufX);
    float* bufY = (float*)sym(g_bufY);

    dim3 exp_blk(64,4);

    // ---- preprocessing (3 launches) ----
    packT_pos_kernel<<<512,256>>>(Apos, apT, pc, cs);
    pack_neg_kernel<<<512,256>>>(Aneg, unionRow, lastT0, pc);
    wprep_kernel<<<1187,256>>>(W_l1,b_l1,W_g1, W_l2,b_l2,W_g2, W_l3,b_l3,W_g3,
                               Wb1,bb1, Wb2,bb2, Wb3,bb3);

    // ---- stage 1: [h1|g1] = x @ Wbig1 + bbig1 (F=256, w=1, relu) ----
    gemm_cs_kernel<<<dim3(8,32),256>>>(x,512, Wb1,512, bb1, bufC,512, 512,512, pc, cs, 256);
    agg_kernel<64,8><<<256,512>>>(bufC,512, bufC+256,512, pc, unionRow, cs, b_g1, bufX,256, 256, 1.0f, 1);

    // ---- stage 2 (F=62, w=1, relu) ----
    expandT_kernel<<<512,exp_blk>>>(lastT0, lastT1, apT, pc, cs);
    transpose_or_kernel<<<64,256>>>(lastT1, unionRow, pc);
    gemm_cs_kernel<<<dim3(2,32),256>>>(bufX,256, Wb2,128, bb2, bufC,128, 256,128, pc, cs, 64);
    agg_kernel<16,16><<<128,256>>>(bufC,128, bufC+64,128, pc, unionRow, cs, b_g2, bufY,64, 62, 1.0f, 1);

    // ---- stage 3 (F=64, w=0.5, relu) ----
    expandT_kernel<<<512,exp_blk>>>(lastT1, lastT0, apT, pc, cs);
    transpose_or_kernel<<<64,256>>>(lastT0, unionRow, pc);
    gemm_cs_kernel<<<dim3(2,32),256>>>(bufY,64, Wb3,128, bb3, bufC,128, 62,128, pc, cs, 64);
    agg_kernel<16,16><<<128,256>>>(bufC,128, bufC+64,128, pc, unionRow, cs, b_g3, bufX,64, 64, 0.5f, 1);

    // ---- stage 4 (h = x3, w=0.5, relu) ----
    expandT_kernel<<<512,exp_blk>>>(lastT0, lastT1, apT, pc, cs);
    transpose_or_kernel<<<64,256>>>(lastT1, unionRow, pc);
    gemm_cs_kernel<<<dim3(1,32),256>>>(bufX,64, W_g4,64, nullptr, bufC,64, 64,64, pc, cs, 0);
    agg_kernel<16,16><<<128,256>>>(bufX,64, bufC,64, pc, unionRow, cs, b_g4, bufY,64, 64, 0.5f, 1);

    // ---- stage 5 (h = x4, w=0.25, relu) ----
    expandT_kernel<<<512,exp_blk>>>(lastT1, lastT0, apT, pc, cs);
    transpose_or_kernel<<<64,256>>>(lastT0, unionRow, pc);
    gemm_cs_kernel<<<dim3(1,32),256>>>(bufY,64, W_g5,64, nullptr, bufC,64, 64,64, pc, cs, 0);
    agg_kernel<16,16><<<128,256>>>(bufY,64, bufC,64, pc, unionRow, cs, b_g5, bufX,64, 64, 0.25f, 1);

    // ---- stage 6 (h = x5, w=0.25, NO relu) -> d_out ----
    expandT_kernel<<<512,exp_blk>>>(lastT0, lastT1, apT, pc, cs);
    transpose_or_kernel<<<64,256>>>(lastT1, unionRow, pc);
    gemm_cs_kernel<<<dim3(1,32),256>>>(bufX,64, W_g6,64, nullptr, bufC,64, 64,64, pc, cs, 0);
    agg_kernel<16,16><<<128,256>>>(bufX,64, bufC,64, pc, unionRow, cs, b_g6, out,64, 64, 0.25f, 0);
}

// round 3
// speedup vs baseline: 2.4828x; 1.0218x over previous
#include <cuda_runtime.h>
#include <stdint.h>

#define NN 2048
#define NW 64   // 2048 bits = 64 u32 words

// ---------------- device scratch ----------------
__device__ uint32_t g_apT[NN*NW];       // A_pos^T bits
__device__ uint32_t g_lastT0[NN*NW];
__device__ uint32_t g_lastT1[NN*NW];
__device__ uint32_t g_unionRow[NN*NW];
__device__ int      g_pc[NN];           // popcount(union row)
__device__ float    g_cs[512];          // column sums of dinv.*g
__device__ float    g_Wbig1[512*512];
__device__ float    g_bbig1[512];
__device__ float    g_Wbig2[256*128];
__device__ float    g_bbig2[128];
__device__ float    g_Wbig3[64*128];
__device__ float    g_bbig3[128];
__device__ float    g_bufC[NN*512];     // GEMM outputs
__device__ float    g_bufX[NN*256];
__device__ float    g_bufY[NN*64];

// ---------------- pack A_pos -> transposed bits only; zero pc & cs ----------------
__global__ void packT_pos_kernel(const float* __restrict__ A, uint32_t* __restrict__ apT,
                                 int* __restrict__ pc, float* __restrict__ cs)
{
    int gwarp = (blockIdx.x*blockDim.x + threadIdx.x) >> 5;
    int lane  = threadIdx.x & 31;
    int ti = gwarp >> 6;   // row tile (32 rows)
    int tj = gwarp & 63;   // col tile (32 cols)
    uint32_t tbits = 0;
#pragma unroll
    for (int r = 0; r < 32; r++) {
        float v = A[(size_t)(ti*32 + r)*NN + tj*32 + lane];
        tbits |= (v > 0.f ? 1u : 0u) << r;
    }
    apT[(tj*32 + lane)*NW + ti] = tbits;
    if (blockIdx.x == 0) {
        for (int t = threadIdx.x; t < NN; t += blockDim.x) pc[t] = 0;
        for (int t = threadIdx.x; t < 512; t += blockDim.x) cs[t] = 0.f;
    }
}

// ---------------- pack A_neg -> unionRow (row bits) + lastT (transposed) + pc ----------------
__global__ void pack_neg_kernel(const float* __restrict__ A, uint32_t* __restrict__ unionRow,
                                uint32_t* __restrict__ lastT, int* __restrict__ pc)
{
    int gwarp = (blockIdx.x*blockDim.x + threadIdx.x) >> 5;
    int lane  = threadIdx.x & 31;
    int ti = gwarp >> 6;
    int tj = gwarp & 63;
    uint32_t tbits = 0, rw = 0;
#pragma unroll
    for (int r = 0; r < 32; r++) {
        float v = A[(size_t)(ti*32 + r)*NN + tj*32 + lane];
        uint32_t b = (v > 0.f) ? 1u : 0u;
        tbits |= b << r;
        uint32_t m = __ballot_sync(0xffffffffu, b);
        if (lane == r) rw = m;
    }
    unionRow[(ti*32 + lane)*NW + tj] = rw;
    atomicAdd(&pc[ti*32 + lane], __popc(rw));
    lastT[(tj*32 + lane)*NW + ti] = tbits;
}

// ---------------- weight pre-association: Wbig = [W_l | W_l@W_g], bbig = [b_l | b_l@W_g] ----------------
__global__ void wprep_kernel(const float* __restrict__ W_l1, const float* __restrict__ b_l1, const float* __restrict__ W_g1,
                             const float* __restrict__ W_l2, const float* __restrict__ b_l2, const float* __restrict__ W_g2,
                             const float* __restrict__ W_l3, const float* __restrict__ b_l3, const float* __restrict__ W_g3,
                             float* __restrict__ Wbig1, float* __restrict__ bbig1,
                             float* __restrict__ Wbig2, float* __restrict__ bbig2,
                             float* __restrict__ Wbig3, float* __restrict__ bbig3)
{
    int idx = blockIdx.x*blockDim.x + threadIdx.x;
    if (idx < 262144) {                       // Wbig1: 512 x 512
        int k = idx >> 9, c = idx & 511;
        float v;
        if (c < 256) v = W_l1[k*256 + c];
        else { float s = 0.f; int cc = c-256; for (int j = 0; j < 256; j++) s += W_l1[k*256+j]*W_g1[j*256+cc]; v = s; }
        Wbig1[idx] = v;
    } else if (idx < 262656) {                // bbig1: 512
        int c = idx - 262144; float v;
        if (c < 256) v = b_l1[c];
        else { float s = 0.f; int cc = c-256; for (int j = 0; j < 256; j++) s += b_l1[j]*W_g1[j*256+cc]; v = s; }
        bbig1[c] = v;
    } else if (idx < 295424) {                // Wbig2: 256 x 128
        int i = idx - 262656; int k = i >> 7, c = i & 127; float v = 0.f;
        if (c < 62) v = W_l2[k*62 + c];
        else if (c >= 64 && c < 126) { float s = 0.f; int cc = c-64; for (int j = 0; j < 62; j++) s += W_l2[k*62+j]*W_g2[j*62+cc]; v = s; }
        Wbig2[i] = v;
    } else if (idx < 295552) {                // bbig2: 128
        int c = idx - 295424; float v = 0.f;
        if (c < 62) v = b_l2[c];
        else if (c >= 64 && c < 126) { float s = 0.f; int cc = c-64; for (int j = 0; j < 62; j++) s += b_l2[j]*W_g2[j*62+cc]; v = s; }
        bbig2[c] = v;
    } else if (idx < 303744) {                // Wbig3: 64 x 128 (rows 62,63 = 0)
        int i = idx - 295552; int k = i >> 7, c = i & 127; float v = 0.f;
        if (k < 62) {
            if (c < 64) v = W_l3[k*64 + c];
            else { float s = 0.f; int cc = c-64; for (int j = 0; j < 64; j++) s += W_l3[k*64+j]*W_g3[j*64+cc]; v = s; }
        }
        Wbig3[i] = v;
    } else if (idx < 303872) {                // bbig3: 128
        int c = idx - 303744; float v;
        if (c < 64) v = b_l3[c];
        else { float s = 0.f; int cc = c-64; for (int j = 0; j < 64; j++) s += b_l3[j]*W_g3[j*64+cc]; v = s; }
        bbig3[c] = v;
    }
}

// ---------------- expansion in transposed domain + zero pc/cs for this stage ----------------
// lastNew[j] = OR_{k in col_j(Ap)} lastOld[k]
__global__ void expandT_kernel(const uint32_t* __restrict__ lastOld, uint32_t* __restrict__ lastNew,
                               const uint32_t* __restrict__ apT, int* __restrict__ pc, float* __restrict__ cs)
{
    __shared__ uint32_t sh[4][64];
    int w = threadIdx.x;                  // 0..63
    int y = threadIdx.y;                  // 0..3
    int j = blockIdx.x*4 + y;
    sh[y][w] = apT[j*NW + w];
    __syncthreads();
    uint32_t acc = 0;
    for (int w2 = 0; w2 < NW; w2++) {
        uint32_t m = sh[y][w2];
        while (m) {
            int b = __ffs(m) - 1; m &= (m-1);
            acc |= lastOld[(w2*32 + b)*NW + w];
        }
    }
    lastNew[j*NW + w] = acc;
    if (blockIdx.x == 0 && y == 0) { for (int t = w; t < NN;  t += 64) pc[t] = 0; }
    if (blockIdx.x == 1 && y == 0) { for (int t = w; t < 512; t += 64) cs[t] = 0.f; }
}

// ---------------- transpose lastNew, OR into unionRow, accumulate pc ----------------
__global__ void transpose_or_kernel(const uint32_t* __restrict__ lastNew,
                                    uint32_t* __restrict__ unionRow, int* __restrict__ pc)
{
    __shared__ uint32_t sh[32][65];
    int tid = threadIdx.x;
    int ti = blockIdx.x;                  // 32 input rows: ti*32..+31
    for (int idx = tid; idx < 32*64; idx += blockDim.x) {
        int r = idx >> 6, c = idx & 63;
        sh[r][c] = lastNew[(ti*32 + r)*NW + c];
    }
    __syncthreads();
    int warp = tid >> 5, lane = tid & 31;
    for (int tj = warp; tj < 64; tj += 8) {
        uint32_t v = sh[lane][tj];
        uint32_t ow = 0;
#pragma unroll
        for (int jb = 0; jb < 32; jb++) {
            uint32_t m = __ballot_sync(0xffffffffu, (v >> jb) & 1u);
            if (lane == jb) ow = m;
        }
        int j = tj*32 + lane;
        uint32_t merged = unionRow[j*NW + ti] | ow;
        unionRow[j*NW + ti] = merged;
        atomicAdd(&pc[j], __popc(merged));
    }
}

// ---------------- tiled SGEMM with bias + fused colsum (cs[c-gOff] += dinv_r * C[r][c]) ----------------
__global__ void gemm_cs_kernel(const float* __restrict__ A, int lda,
                               const float* __restrict__ W, int ldw,
                               const float* __restrict__ bias,
                               float* __restrict__ C, int ldc,
                               int K, int N,
                               const int* __restrict__ pc,
                               float* __restrict__ cs, int gOff)
{
    __shared__ __align__(16) float As[8][68];
    __shared__ __align__(16) float Ws[8][64];
    __shared__ float red[16][64];
    int tid = threadIdx.x;
    int tx = tid & 15, ty = tid >> 4;
    int rowBase = blockIdx.y * 64;
    int colBase = blockIdx.x * 64;

    float acc[4][4];
#pragma unroll
    for (int a = 0; a < 4; a++)
#pragma unroll
        for (int b = 0; b < 4; b++) acc[a][b] = 0.f;

    for (int k0 = 0; k0 < K; k0 += 8) {
        {
            int m  = tid >> 2;
            int kb = (tid & 3) * 2;
#pragma unroll
            for (int l = 0; l < 2; l++) {
                int kk = kb + l;
                As[kk][m] = (k0+kk < K) ? A[(size_t)(rowBase+m)*lda + k0 + kk] : 0.f;
            }
        }
        {
            int kk = tid >> 5;
            int nb = (tid & 31) * 2;
#pragma unroll
            for (int l = 0; l < 2; l++) {
                int n = nb + l;
                Ws[kk][n] = (k0+kk < K) ? W[(size_t)(k0+kk)*ldw + colBase + n] : 0.f;
            }
        }
        __syncthreads();
#pragma unroll
        for (int kk = 0; kk < 8; kk++) {
            float4 av = *(const float4*)&As[kk][ty*4];
            float4 bv = *(const float4*)&Ws[kk][tx*4];
            float a4[4] = {av.x, av.y, av.z, av.w};
            float b4[4] = {bv.x, bv.y, bv.z, bv.w};
#pragma unroll
            for (int a = 0; a < 4; a++)
#pragma unroll
                for (int b = 0; b < 4; b++)
                    acc[a][b] += a4[a] * b4[b];
        }
        __syncthreads();
    }

    float p[4] = {0.f, 0.f, 0.f, 0.f};
#pragma unroll
    for (int a = 0; a < 4; a++) {
        int row = rowBase + ty*4 + a;
        float di = rsqrtf((float)(pc[row] + 1));
#pragma unroll
        for (int b = 0; b < 4; b++) {
            int col = colBase + tx*4 + b;
            float val = acc[a][b] + (bias ? bias[col] : 0.f);
            C[(size_t)row*ldc + col] = val;
            if (col >= gOff) p[b] += di * val;
        }
    }
#pragma unroll
    for (int b = 0; b < 4; b++) red[ty][tx*4 + b] = p[b];
    __syncthreads();
    if (tid < 64) {
        int col = colBase + tid;
        if (col >= gOff) {
            float s = 0.f;
#pragma unroll
            for (int t = 0; t < 16; t++) s += red[t][tid];
            atomicAdd(&cs[col - gOff], s);
        }
    }
}

// ---------------- syncless fused aggregation + GCN epilogue ----------------
// out = h + w*act( dinv_i*(S + dinv_i*g_i) + b ),  S = sum_{k in union row} dinv_k g_k
// complement trick: if pc>1024, S = cs - sum over UNSET bits.
template<int LANES, int RPB>
__global__ void agg_kernel(const float* __restrict__ h, int ldh,
                           const float* __restrict__ g, int ldg,
                           const int* __restrict__ pc,
                           const uint32_t* __restrict__ unionRow,
                           const float* __restrict__ cs,
                           const float* __restrict__ bias,
                           float* __restrict__ out, int ldo,
                           int Nf, float wscale, int doRelu)
{
    int tid = threadIdx.x;
    int flane = tid % LANES;
    int grp = tid / LANES;
    int row = blockIdx.x*RPB + grp;
    int f = flane*4;
    int myPc = pc[row];
    bool comp = myPc > 1024;
    float di = rsqrtf((float)(myPc + 1));
    float4 acc = make_float4(0.f,0.f,0.f,0.f);
    const uint32_t* ur = unionRow + row*NW;
    for (int w2 = 0; w2 < NW; w2++) {
        uint32_t m = ur[w2];
        if (comp) m = ~m;
        int kbase = w2*32;
        while (m) {
            int b = __ffs(m) - 1; m &= (m-1);
            int k = kbase + b;
            float dk = rsqrtf((float)(pc[k] + 1));
            float4 v = *(const float4*)(g + (size_t)k*ldg + f);
            acc.x += dk*v.x; acc.y += dk*v.y; acc.z += dk*v.z; acc.w += dk*v.w;
        }
    }
    float S[4] = {acc.x, acc.y, acc.z, acc.w};
    if (comp) {
        float4 c4 = *(const float4*)(cs + f);
        S[0] = c4.x - S[0]; S[1] = c4.y - S[1]; S[2] = c4.z - S[2]; S[3] = c4.w - S[3];
    }
    float4 gi = *(const float4*)(g + (size_t)row*ldg + f);
    float4 hv = *(const float4*)(h + (size_t)row*ldh + f);
    float gia[4] = {gi.x, gi.y, gi.z, gi.w};
    float ha[4]  = {hv.x, hv.y, hv.z, hv.w};
#pragma unroll
    for (int c = 0; c < 4; c++) {
        int ff = f + c;
        if (ff < Nf) {
            float val = di*(S[c] + di*gia[c]) + bias[ff];
            if (doRelu) val = fmaxf(val, 0.f);
            out[(size_t)row*ldo + ff] = ha[c] + wscale*val;
        }
    }
}

// ---------------- host ----------------
static void* sym(const void* s) { void* p = nullptr; cudaGetSymbolAddress(&p, s); return p; }

extern "C" void kernel_launch(void* const* d_in, const int* in_sizes, int n_in,
                              void* d_out, int out_size)
{
    const float* x    = (const float*)d_in[0];
    const float* Aneg = (const float*)d_in[1];
    const float* Apos = (const float*)d_in[2];
    const float* W_l1 = (const float*)d_in[3];  const float* b_l1 = (const float*)d_in[4];
    const float* W_l2 = (const float*)d_in[5];  const float* b_l2 = (const float*)d_in[6];
    const float* W_l3 = (const float*)d_in[7];  const float* b_l3 = (const float*)d_in[8];
    const float* W_g1 = (const float*)d_in[9];  const float* b_g1 = (const float*)d_in[10];
    const float* W_g2 = (const float*)d_in[11]; const float* b_g2 = (const float*)d_in[12];
    const float* W_g3 = (const float*)d_in[13]; const float* b_g3 = (const float*)d_in[14];
    const float* W_g4 = (const float*)d_in[15]; const float* b_g4 = (const float*)d_in[16];
    const float* W_g5 = (const float*)d_in[17]; const float* b_g5 = (const float*)d_in[18];
    const float* W_g6 = (const float*)d_in[19]; const float* b_g6 = (const float*)d_in[20];
    float* out = (float*)d_out;

    uint32_t* apT      = (uint32_t*)sym(g_apT);
    uint32_t* lastT0   = (uint32_t*)sym(g_lastT0);
    uint32_t* lastT1   = (uint32_t*)sym(g_lastT1);
    uint32_t* unionRow = (uint32_t*)sym(g_unionRow);
    int*   pc   = (int*)sym(g_pc);
    float* cs   = (float*)sym(g_cs);
    float* Wb1  = (float*)sym(g_Wbig1); float* bb1 = (float*)sym(g_bbig1);
    float* Wb2  = (float*)sym(g_Wbig2); float* bb2 = (float*)sym(g_bbig2);
    float* Wb3  = (float*)sym(g_Wbig3); float* bb3 = (float*)sym(g_bbig3);
    float* bufC = (float*)sym(g_bufC);
    float* bufX = (float*)sym(g_bufX);
    float* bufY = (float*)sym(g_bufY);

    dim3 exp_blk(64,4);

    // ---- preprocessing (3 launches) ----
    packT_pos_kernel<<<512,256>>>(Apos, apT, pc, cs);
    pack_neg_kernel<<<512,256>>>(Aneg, unionRow, lastT0, pc);
    wprep_kernel<<<1187,256>>>(W_l1,b_l1,W_g1, W_l2,b_l2,W_g2, W_l3,b_l3,W_g3,
                               Wb1,bb1, Wb2,bb2, Wb3,bb3);

    // ---- stage 1: [h1|g1] = x @ Wbig1 + bbig1 (F=256, w=1, relu) ----
    gemm_cs_kernel<<<dim3(8,32),256>>>(x,512, Wb1,512, bb1, bufC,512, 512,512, pc, cs, 256);
    agg_kernel<64,8><<<256,512>>>(bufC,512, bufC+256,512, pc, unionRow, cs, b_g1, bufX,256, 256, 1.0f, 1);

    // ---- stage 2 (F=62, w=1, relu) ----
    expandT_kernel<<<512,exp_blk>>>(lastT0, lastT1, apT, pc, cs);
    transpose_or_kernel<<<64,256>>>(lastT1, unionRow, pc);
    gemm_cs_kernel<<<dim3(2,32),256>>>(bufX,256, Wb2,128, bb2, bufC,128, 256,128, pc, cs, 64);
    agg_kernel<16,16><<<128,256>>>(bufC,128, bufC+64,128, pc, unionRow, cs, b_g2, bufY,64, 62, 1.0f, 1);

    // ---- stage 3 (F=64, w=0.5, relu) ----
    expandT_kernel<<<512,exp_blk>>>(lastT1, lastT0, apT, pc, cs);
    transpose_or_kernel<<<64,256>>>(lastT0, unionRow, pc);
    gemm_cs_kernel<<<dim3(2,32),256>>>(bufY,64, Wb3,128, bb3, bufC,128, 62,128, pc, cs, 64);
    agg_kernel<16,16><<<128,256>>>(bufC,128, bufC+64,128, pc, unionRow, cs, b_g3, bufX,64, 64, 0.5f, 1);

    // ---- stage 4 (h = x3, w=0.5, relu) ----
    expandT_kernel<<<512,exp_blk>>>(lastT0, lastT1, apT, pc, cs);
    transpose_or_kernel<<<64,256>>>(lastT1, unionRow, pc);
    gemm_cs_kernel<<<dim3(1,32),256>>>(bufX,64, W_g4,64, nullptr, bufC,64, 64,64, pc, cs, 0);
    agg_kernel<16,16><<<128,256>>>(bufX,64, bufC,64, pc, unionRow, cs, b_g4, bufY,64, 64, 0.5f, 1);

    // ---- stage 5 (h = x4, w=0.25, relu) ----
    expandT_kernel<<<512,exp_blk>>>(lastT1, lastT0, apT, pc, cs);
    transpose_or_kernel<<<64,256>>>(lastT0, unionRow, pc);
    gemm_cs_kernel<<<dim3(1,32),256>>>(bufY,64, W_g5,64, nullptr, bufC,64, 64,64, pc, cs, 0);
    agg_kernel<16,16><<<128,256>>>(bufY,64, bufC,64, pc, unionRow, cs, b_g5, bufX,64, 64, 0.25f, 1);

    // ---- stage 6 (h = x5, w=0.25, NO relu) -> d_out ----
    expandT_kernel<<<512,exp_blk>>>(lastT0, lastT1, apT, pc, cs);
    transpose_or_kernel<<<64,256>>>(lastT1, unionRow, pc);
    gemm_cs_kernel<<<dim3(1,32),256>>>(bufX,64, W_g6,64, nullptr, bufC,64, 64,64, pc, cs, 0);
    agg_kernel<16,16><<<128,256>>>(bufX,64, bufC,64, pc, unionRow, cs, b_g6, out,64, 64, 0.25f, 0);
}